// round 8
// baseline (speedup 1.0000x reference)
#include <cuda_runtime.h>
#include <math.h>

#define F 256
#define NC 8
#define SC 16
#define NSTEP 4
#define MAXN 200704
#define BMPW (MAXN/32)
#define CANDCAP 2048
#define EPSF 1e-8f
#define NT 512
#define NWARP 16
#define GEMMB 16
#define NMARK (NC*SC)
#define CHUNKI4 2048

#define OUT_OFF 0
#define SEL_OFF  (NSTEP*NC*SC*NC)            /* 4096 */
#define STEP_OFF (SEL_OFF + NSTEP*NC*SC)     /* 4608 */
#define HX_OFF   (STEP_OFF + NSTEP*NC)       /* 4640 */

// ---------------- device state ----------------
__device__ unsigned       g_counts[MAXN*2];   // packed u8 counts, 4 classes/u32
__device__ unsigned char  g_entity[MAXN];
__device__ unsigned       g_cg[MAXN];         // class membership mask
__device__ unsigned       g_candBit[BMPW];    // "already in candidate list"
__device__ int            g_cand[CANDCAP];
__device__ int            g_candCount;
__device__ float          g_inp[NC*F];
__device__ float          g_hx[NC*F];
__device__ float          g_hxden[NC];
__device__ float          g_gi[NC*3*F];
__device__ float          g_gh[NC*3*F];
__device__ int            g_selNode[NMARK];
__device__ unsigned char  g_selVm[NMARK];
__device__ int            g_mlNode[NMARK];    // mark list: node
__device__ unsigned       g_mlBit[NMARK];     // mark list: class bit (0 = not new)
__device__ int            g_chunk[NSTEP];     // steal counters (zeroed in P0)
__device__ unsigned       g_barArrive;
__device__ unsigned       g_barGen;

union SH {
    float shv[2*NC*F];                        // 16KB (gemm)
    struct {                                  // edge scan ~26KB
        unsigned bmp[BMPW];
        int mnode[NMARK];
        unsigned mbit[NMARK];
    } scan;
    struct {                                  // select (D) ~19.7KB
        unsigned long long keys[CANDCAP];
        unsigned long long red[NWARP];
        unsigned long long bestk;
        float hxc[F];
        unsigned char vmask[CANDCAP];
        unsigned char fillv[64];
        unsigned char selvm[SC];
        int snode[SC];
        float hxden_c;
    } d;
    struct {                                  // output rows ~8.7KB
        float hxs[NC*F];
        float hxden[NC];
        int node[NMARK];
        unsigned char vm[NMARK];
    } rows;
};

// ---------------- grid barrier (reset-free, replay-safe, backoff spin) -----
__device__ __forceinline__ void gsync(unsigned barBase, unsigned &nbar, int NB) {
    __syncthreads();
    if (threadIdx.x == 0) {
        __threadfence();
        unsigned target = barBase + nbar + 1u;
        unsigned t = atomicAdd(&g_barArrive, 1u);
        if (t == target * (unsigned)NB - 1u) {
            *(volatile unsigned*)&g_barGen = target;       // release
        } else {
            while (*(volatile unsigned*)&g_barGen - barBase < nbar + 1u)
                __nanosleep(32);
        }
        __threadfence();                                    // acquire
    }
    __syncthreads();
    nbar++;
}

// all threads participate; result valid on thread 0
__device__ __forceinline__ float blockSumAll(float v, float* red) {
    int lane = threadIdx.x & 31, w = threadIdx.x >> 5;
    #pragma unroll
    for (int o = 16; o; o >>= 1) v += __shfl_down_sync(0xffffffffu, v, o);
    if (lane == 0) red[w] = v;
    __syncthreads();
    float r = 0.f;
    if (w == 0) {
        r = (lane < NWARP) ? red[lane] : 0.f;
        #pragma unroll
        for (int o = 8; o; o >>= 1) r += __shfl_down_sync(0xffffffffu, r, o);
    }
    __syncthreads();
    return r;
}

__device__ __forceinline__ unsigned validMask(int i, int mm) {
    if (g_entity[i]) return 0u;
    uint2 u = *(const uint2*)&g_counts[(size_t)i * 2];
    unsigned vm = 0;
    #pragma unroll
    for (int c = 0; c < 4; c++)
        if (((u.x >> (c * 8)) & 0xffu) >= (unsigned)mm) vm |= 1u << c;
    #pragma unroll
    for (int c = 0; c < 4; c++)
        if (((u.y >> (c * 8)) & 0xffu) >= (unsigned)mm) vm |= 1u << (c + 4);
    return vm;
}

// rare path: resolve a hit edge against the 128-entry mark list
__device__ __noinline__ void hitEdge(SH& sh, int src, int dst) {
    #pragma unroll 1
    for (int j = 0; j < NMARK; j++) {
        if (sh.scan.mnode[j] == dst) {
            unsigned b = sh.scan.mbit[j];
            if (b) {
                int c = __ffs(b) - 1;
                int w = c >> 2, sh8 = (c & 3) * 8;
                unsigned old = atomicAdd(&g_counts[(size_t)src * 2 + w], 1u << sh8);
                if (((old >> sh8) & 0xffu) == 1u && !g_entity[src]) {
                    unsigned ob = atomicOr(&g_candBit[(unsigned)src >> 5], 1u << (src & 31));
                    if (!((ob >> (src & 31)) & 1u)) {
                        int p = atomicAdd(&g_candCount, 1);
                        if (p < CANDCAP) g_cand[p] = src;
                    }
                }
            }
        }
    }
}

#define PROBE(dd, jj) do {                                                   \
    unsigned _h0 = (sh.scan.bmp[(unsigned)(dd).x >> 5] >> ((dd).x & 31)) & 1u; \
    unsigned _h1 = (sh.scan.bmp[(unsigned)(dd).y >> 5] >> ((dd).y & 31)) & 1u; \
    unsigned _h2 = (sh.scan.bmp[(unsigned)(dd).z >> 5] >> ((dd).z & 31)) & 1u; \
    unsigned _h3 = (sh.scan.bmp[(unsigned)(dd).w >> 5] >> ((dd).w & 31)) & 1u; \
    if (_h0 | _h1 | _h2 | _h3) {                                             \
        int4 _s = s4[jj];                                                    \
        if (_h0) hitEdge(sh, _s.x, (dd).x);                                  \
        if (_h1) hitEdge(sh, _s.y, (dd).y);                                  \
        if (_h2) hitEdge(sh, _s.z, (dd).z);                                  \
        if (_h3) hitEdge(sh, _s.w, (dd).w);                                  \
    } } while (0)

// work-stealing edge scan; builds smem bitmap from mark list
__device__ void edgeScanSteal(SH& sh, int* curChunk, const int* __restrict__ esrc,
                              const int* __restrict__ edst, int E, int step, int bid) {
    int tid = threadIdx.x;
    for (int i = tid; i < BMPW; i += NT) sh.scan.bmp[i] = 0u;
    if (tid < NMARK) {
        sh.scan.mnode[tid] = g_mlNode[tid];
        sh.scan.mbit[tid] = g_mlBit[tid];
    }
    __syncthreads();
    if (tid < NMARK && sh.scan.mbit[tid])
        atomicOr(&sh.scan.bmp[(unsigned)sh.scan.mnode[tid] >> 5],
                 1u << (sh.scan.mnode[tid] & 31));

    int e4 = E >> 2;
    int nchunk = (e4 + CHUNKI4 - 1) / CHUNKI4;
    const int4* d4 = (const int4*)edst;
    const int4* s4 = (const int4*)esrc;
    for (;;) {
        __syncthreads();
        if (tid == 0) *curChunk = atomicAdd(&g_chunk[step], 1);
        __syncthreads();
        int t = *curChunk;
        if (t >= nchunk) break;
        int base = t * CHUNKI4;
        int end = base + CHUNKI4; if (end > e4) end = e4;
        #pragma unroll 4
        for (int j = base + tid; j < end; j += NT) {
            int4 d = d4[j];
            PROBE(d, j);
        }
    }
    if (bid == GEMMB && tid == 0) {
        for (int e = e4 << 2; e < E; ++e) {
            int d = edst[e];
            if ((sh.scan.bmp[(unsigned)d >> 5] >> (d & 31)) & 1u)
                hitEdge(sh, esrc[e], d);
        }
    }
}

// warp: norm + 8 class dots of a 256-float row vs smem hx (lane 0 gets results)
__device__ __forceinline__ void warpScore8(const float* __restrict__ esrow,
                                           const float* hxs, float* dots, float* den) {
    int lane = threadIdx.x & 31;
    const float4* r4 = (const float4*)(esrow + lane * 8);
    float4 a = r4[0], b = r4[1];
    float x[8] = {a.x, a.y, a.z, a.w, b.x, b.y, b.z, b.w};
    float acc[9];
    #pragma unroll
    for (int k = 0; k < 9; k++) acc[k] = 0.f;
    #pragma unroll
    for (int k = 0; k < 8; k++) acc[8] += x[k] * x[k];
    #pragma unroll
    for (int c = 0; c < NC; c++) {
        const float* h = hxs + c * F + lane * 8;
        #pragma unroll
        for (int k = 0; k < 8; k++) acc[c] += x[k] * h[k];
    }
    #pragma unroll
    for (int o = 16; o; o >>= 1) {
        #pragma unroll
        for (int k = 0; k < 9; k++)
            acc[k] += __shfl_down_sync(0xffffffffu, acc[k], o);
    }
    #pragma unroll
    for (int c = 0; c < NC; c++) dots[c] = acc[c];
    *den = sqrtf(acc[8]) + EPSF;
}

// warp: norm + 1 dot vs smem hx_c (lane 0 gets results)
__device__ __forceinline__ void warpScore1(const float* __restrict__ esrow,
                                           const float* hxc, float* dot, float* den) {
    int lane = threadIdx.x & 31;
    const float4* r4 = (const float4*)(esrow + lane * 8);
    float4 a = r4[0], b = r4[1];
    float x[8] = {a.x, a.y, a.z, a.w, b.x, b.y, b.z, b.w};
    const float* h = hxc + lane * 8;
    float d0 = 0.f, n0 = 0.f;
    #pragma unroll
    for (int k = 0; k < 8; k++) { d0 += x[k] * h[k]; n0 += x[k] * x[k]; }
    #pragma unroll
    for (int o = 16; o; o >>= 1) {
        d0 += __shfl_down_sync(0xffffffffu, d0, o);
        n0 += __shfl_down_sync(0xffffffffu, n0, o);
    }
    *dot = d0;
    *den = sqrtf(n0) + EPSF;
}

// output rows for `step` using current g_hx/g_selNode/g_selVm (blocks 8..15)
__device__ void outRows(SH& sh, const float* __restrict__ es,
                        float* __restrict__ out, int step, int bid) {
    int tid = threadIdx.x, wid = tid >> 5, lane = tid & 31;
    for (int i = tid; i < NC * F; i += NT) sh.rows.hxs[i] = g_hx[i];
    if (tid < NC) sh.rows.hxden[tid] = g_hxden[tid];
    if (tid < NMARK) {
        sh.rows.node[tid] = g_selNode[tid];
        sh.rows.vm[tid] = g_selVm[tid];
    }
    __syncthreads();
    int rw = (bid - 8) * NWARP + wid;   // 0..127
    int node = sh.rows.node[rw];
    unsigned vm = sh.rows.vm[rw];
    float* orow = out + OUT_OFF + step * (NC * SC * NC) + rw * NC;
    if (vm == 0u) {
        if (lane < NC) orow[lane] = 0.f;
    } else {
        float dots[NC], den;
        warpScore8(es + (size_t)node * F, sh.rows.hxs, dots, &den);
        if (lane == 0) {
            #pragma unroll
            for (int c2 = 0; c2 < NC; c2++)
                orow[c2] = 0.5f * (dots[c2] / (den * sh.rows.hxden[c2])) + 0.5f;
        }
    }
}

__global__ __launch_bounds__(NT, 1) void fused_kernel(
    const int* __restrict__ seeds, const int* __restrict__ esrc,
    const int* __restrict__ edst, const float* __restrict__ es,
    const float* __restrict__ W_ih, const float* __restrict__ W_hh,
    const float* __restrict__ b_ih, const float* __restrict__ b_hh,
    float* __restrict__ out, int E, int n)
{
    __shared__ SH sh;
    __shared__ float redsm[NWARP];
    __shared__ unsigned sBase;
    __shared__ int curChunk;
    const int NB = gridDim.x;
    const int tid = threadIdx.x, bid = blockIdx.x;
    const int gid = bid * NT + tid, GT = NB * NT;
    const int wid = tid >> 5, lane = tid & 31;

    if (tid == 0) sBase = *(volatile unsigned*)&g_barGen;
    __syncthreads();
    const unsigned barBase = sBase;
    unsigned nbar = 0;

    // ---- P0: zero state ----
    for (int i = gid; i < 2 * n; i += GT) g_counts[i] = 0u;
    for (int i = gid; i < n; i += GT) { g_entity[i] = 0; g_cg[i] = 0u; }
    for (int i = gid; i < BMPW; i += GT) g_candBit[i] = 0u;
    for (int i = gid; i < NC * F; i += GT) g_hx[i] = 0.f;
    if (gid == 0) {
        g_candCount = 0;
        #pragma unroll
        for (int s = 0; s < NSTEP; s++) g_chunk[s] = 0;
    }
    gsync(barBase, nbar, NB);

    // ---- P1: seed marks + pool from seeds ----
    if (bid == 0 && tid < NMARK) {
        int s = seeds[tid], c = tid >> 4;
        g_entity[s] = 1;
        atomicOr(&g_cg[s], 1u << c);
        g_mlNode[tid] = s;
        g_mlBit[tid] = 1u << c;
    }
    if (bid >= 1 && bid <= NC && tid < F) {
        int c = bid - 1;
        float s = 0.f;
        #pragma unroll
        for (int j = 0; j < SC; j++)
            s += es[(size_t)seeds[c * SC + j] * F + tid];
        g_inp[c * F + tid] = s * (1.0f / SC);
    }
    gsync(barBase, nbar, NB);

    for (int step = 0; step < NSTEP; step++) {
        int mm = (step == 0) ? 3 : 2;

        // ---- A: gemm + mark-apply + prev rows (blocks 0-15) || steal scan ----
        if (bid < GEMMB) {
            // block 0 applies previous step's marks (ordered before D by barrier)
            if (bid == 0 && step > 0 && tid < NMARK) {
                int node = g_mlNode[tid];
                unsigned b = g_mlBit[tid];
                g_entity[node] = 1;
                if (b) atomicOr(&g_cg[node], b);
            }
            for (int i = tid; i < NC * F; i += NT) {
                sh.shv[i] = g_inp[i];
                sh.shv[NC * F + i] = g_hx[i];
            }
            __syncthreads();
            int warp = bid * NWARP + wid;
            int totalW = GEMMB * NWARP;
            for (int job = warp; job < 2 * 3 * F; job += totalW) {
                int m = (job >= 3 * F) ? 1 : 0;
                int r = job - m * 3 * F;
                const float4* w4 = (const float4*)((m ? W_hh : W_ih) + (size_t)r * F);
                float4 a = w4[lane * 2], b = w4[lane * 2 + 1];
                float wv[8] = {a.x, a.y, a.z, a.w, b.x, b.y, b.z, b.w};
                const float* vecb = sh.shv + m * NC * F;
                #pragma unroll
                for (int c = 0; c < NC; c++) {
                    const float* v = vecb + c * F + lane * 8;
                    float d = wv[0]*v[0] + wv[1]*v[1] + wv[2]*v[2] + wv[3]*v[3]
                            + wv[4]*v[4] + wv[5]*v[5] + wv[6]*v[6] + wv[7]*v[7];
                    #pragma unroll
                    for (int o = 16; o; o >>= 1) d += __shfl_down_sync(0xffffffffu, d, o);
                    if (lane == 0) (m ? g_gh : g_gi)[c * 3 * F + r] = d;
                }
            }
            if (bid >= 8 && step > 0) {
                __syncthreads();
                outRows(sh, es, out, step - 1, bid);
            }
        } else {
            edgeScanSteal(sh, &curChunk, esrc, edst, E, step, bid);
        }
        gsync(barBase, nbar, NB);

        // ---- D: per-class gate + score + select + fill + pool (read-only masks) ----
        if (bid < NC) {
            int c = bid;
            // gate
            float h = 0.f;
            if (tid < F) {
                int k = tid;
                float gir = g_gi[c*3*F + k]       + b_ih[k];
                float giz = g_gi[c*3*F + F + k]   + b_ih[F + k];
                float gin = g_gi[c*3*F + 2*F + k] + b_ih[2*F + k];
                float ghr = g_gh[c*3*F + k]       + b_hh[k];
                float ghz = g_gh[c*3*F + F + k]   + b_hh[F + k];
                float ghn = g_gh[c*3*F + 2*F + k] + b_hh[2*F + k];
                float r = 1.f / (1.f + expf(-(gir + ghr)));
                float z = 1.f / (1.f + expf(-(giz + ghz)));
                float nn = tanhf(gin + r * ghn);
                h = (1.f - z) * nn + z * g_hx[c * F + k];
                g_hx[c * F + k] = h;
                out[HX_OFF + step * NC * F + c * F + k] = h;
                sh.d.hxc[k] = h;
            }
            float s2 = blockSumAll(h * h, redsm);
            if (tid == 0) {
                float dn = sqrtf(s2) + EPSF;
                sh.d.hxden_c = dn;
                g_hxden[c] = dn;
            }
            __syncthreads();

            int cc = g_candCount; if (cc > CANDCAP) cc = CANDCAP;
            for (int j = tid; j < cc; j += NT)
                sh.d.vmask[j] = (unsigned char)validMask(g_cand[j], mm);
            if (tid < 64) sh.d.fillv[tid] = (unsigned char)validMask(tid, mm);
            __syncthreads();

            // scores -> keys (warp per candidate)
            for (int ci = wid; ci < cc; ci += NWARP) {
                if ((sh.d.vmask[ci] >> c) & 1u) {
                    int node = g_cand[ci];
                    float dot, den;
                    warpScore1(es + (size_t)node * F, sh.d.hxc, &dot, &den);
                    if (lane == 0) {
                        float sc = 0.5f * (dot / (den * sh.d.hxden_c)) + 0.5f;
                        unsigned u = __float_as_uint(sc);
                        u ^= (u & 0x80000000u) ? 0xffffffffu : 0x80000000u;
                        sh.d.keys[ci] = (((unsigned long long)u) << 32)
                                      | (unsigned long long)(~(unsigned)node);
                    }
                } else if (lane == 0) {
                    sh.d.keys[ci] = 0ull;
                }
            }
            __syncthreads();

            // 16-round argmax select (top_k semantics: score desc, index asc)
            int slot = 0;
            for (; slot < SC; ++slot) {
                unsigned long long best = 0ull;
                for (int j = tid; j < cc; j += NT) {
                    unsigned long long k = sh.d.keys[j];
                    if (k > best) best = k;
                }
                #pragma unroll
                for (int o = 16; o; o >>= 1) {
                    unsigned long long v = __shfl_down_sync(0xffffffffu, best, o);
                    if (v > best) best = v;
                }
                if (lane == 0) sh.d.red[wid] = best;
                __syncthreads();
                if (wid == 0) {
                    unsigned long long v = (lane < NWARP) ? sh.d.red[lane] : 0ull;
                    #pragma unroll
                    for (int o = 8; o; o >>= 1) {
                        unsigned long long w = __shfl_down_sync(0xffffffffu, v, o);
                        if (w > v) v = w;
                    }
                    if (lane == 0) sh.d.bestk = v;
                }
                __syncthreads();
                unsigned long long bk = sh.d.bestk;
                if (bk == 0ull) break;
                for (int j = tid; j < cc; j += NT) {
                    if (sh.d.keys[j] == bk) {
                        sh.d.keys[j] = 0ull;
                        sh.d.selvm[slot] = sh.d.vmask[j];
                    }
                }
                int node = (int)(~(unsigned)(bk & 0xffffffffu));
                if (tid == 0) {
                    sh.d.snode[slot] = node;
                    out[SEL_OFF + step * NC * SC + c * SC + slot] = (float)node;
                }
                __syncthreads();
            }
            // fill: smallest indices not valid-for-c (pre-step masks, race-free)
            if (tid == 0) {
                int p = 0;
                for (; slot < SC; ++slot) {
                    unsigned fv;
                    for (;;) {
                        fv = (p < 64) ? (unsigned)sh.d.fillv[p] : validMask(p, mm);
                        if (!((fv >> c) & 1u)) break;
                        ++p;
                    }
                    sh.d.snode[slot] = p;
                    sh.d.selvm[slot] = (unsigned char)fv;
                    out[SEL_OFF + step * NC * SC + c * SC + slot] = (float)p;
                    ++p;
                }
                out[STEP_OFF + step * NC + c] = 16.0f;
            }
            __syncthreads();
            if (tid < SC) {
                int node = sh.d.snode[tid];
                g_selNode[c * SC + tid] = node;
                g_selVm[c * SC + tid] = sh.d.selvm[tid];
                if (step < NSTEP - 1) {
                    unsigned cg = g_cg[node];        // pre-step state (read-only)
                    g_mlNode[c * SC + tid] = node;
                    g_mlBit[c * SC + tid] = ((cg >> c) & 1u) ? 0u : (1u << c);
                }
            }
            // pool for next step
            if (step < NSTEP - 1 && tid < F) {
                float s = 0.f;
                #pragma unroll
                for (int j = 0; j < SC; j++)
                    s += es[(size_t)sh.d.snode[j] * F + tid];
                g_inp[c * F + tid] = s * (1.0f / SC);
            }
        }
        gsync(barBase, nbar, NB);
    }

    // ---- tail: output rows for the last step (blocks 8-15), no barrier ----
    if (bid >= 8 && bid < GEMMB) {
        outRows(sh, es, out, NSTEP - 1, bid);
    }
}

// ---------------- launch ----------------
extern "C" void kernel_launch(void* const* d_in, const int* in_sizes, int n_in,
                              void* d_out, int out_size) {
    const int*   seeds = (const int*)d_in[0];
    const int*   esrc  = (const int*)d_in[1];
    const int*   edst  = (const int*)d_in[2];
    const float* es    = (const float*)d_in[3];
    const float* W_ih  = (const float*)d_in[4];
    const float* W_hh  = (const float*)d_in[5];
    const float* b_ih  = (const float*)d_in[6];
    const float* b_hh  = (const float*)d_in[7];
    float* out = (float*)d_out;
    int E = in_sizes[1];
    int n = in_sizes[3] / F;

    int dev = 0, nsm = 0;
    cudaGetDevice(&dev);
    cudaDeviceGetAttribute(&nsm, cudaDevAttrMultiProcessorCount, dev);
    if (nsm <= 0 || nsm > 512) nsm = 148;

    fused_kernel<<<nsm, NT>>>(seeds, esrc, edst, es, W_ih, W_hh, b_ih, b_hh, out, E, n);
}

// round 10
// speedup vs baseline: 1.4237x; 1.4237x over previous
#include <cuda_runtime.h>
#include <math.h>

#define F 256
#define NC 8
#define SC 16
#define NSTEP 4
#define MAXN 200704
#define BMPW (MAXN/32)
#define CANDCAP 4096
#define EPSF 1e-8f
#define NT 512
#define NWARP (NT/32)
#define GEMMB 16

#define OUT_OFF 0
#define SEL_OFF  (NSTEP*NC*SC*NC)            /* 4096 */
#define STEP_OFF (SEL_OFF + NSTEP*NC*SC)     /* 4608 */
#define HX_OFF   (STEP_OFF + NSTEP*NC)       /* 4640 */

// ---------------- device state ----------------
__device__ unsigned       g_counts[MAXN*2];   // packed u8 counts, 4 classes/u32
__device__ unsigned char  g_entity[MAXN];
__device__ unsigned       g_cg[MAXN];         // class membership mask
__device__ unsigned       g_newMask[MAXN];    // newly marked class bits
__device__ unsigned       g_bitmap[BMPW];     // "has new mark" bit per node
__device__ unsigned char  g_valid[MAXN];
__device__ int            g_cand[CANDCAP];
__device__ int            g_candCount;
__device__ float          g_candScore[CANDCAP*NC];
__device__ float          g_inp[NC*F];
__device__ float          g_hx[NC*F];
__device__ float          g_hxden[NC];
__device__ float          g_gi[NC*3*F];
__device__ float          g_gh[NC*3*F];
__device__ int            g_selNode[NC*SC];
__device__ unsigned char  g_selVm[NC*SC];
__device__ int            g_markNode[NC*SC];
__device__ unsigned       g_barArrive;
__device__ unsigned       g_barGen;

union SH {
    float    shv[2*NC*F];                    // 16KB (gemm)
    unsigned bmp[BMPW];                      // 25KB (edge scan)
    float    hxsc[NC*F];                     // 8KB  (score)
    struct {                                 // select+finalize
        float hxs[NC*F];                     // 8KB
        unsigned long long red[NWARP];
        unsigned long long bestk;
        unsigned ch[CANDCAP/32];
        int snode[SC];
    } sel;
};

// ---------------- grid barrier (reset-free, replay-safe) ----------------
__device__ __forceinline__ void gsync(unsigned barBase, unsigned &nbar, int NB) {
    __syncthreads();
    if (threadIdx.x == 0) {
        __threadfence();
        unsigned target = barBase + nbar + 1u;
        unsigned t = atomicAdd(&g_barArrive, 1u);
        if (t == target * (unsigned)NB - 1u) {
            *(volatile unsigned*)&g_barGen = target;       // release
        } else {
            while (*(volatile unsigned*)&g_barGen - barBase < nbar + 1u)
                __nanosleep(32);
        }
        __threadfence();                                    // acquire
    }
    __syncthreads();
    nbar++;
}

// all threads participate; inactive contribute 0; result valid on thread 0
__device__ __forceinline__ float blockSumAll(float v, float* red) {
    int lane = threadIdx.x & 31, w = threadIdx.x >> 5;
    #pragma unroll
    for (int o = 16; o; o >>= 1) v += __shfl_down_sync(0xffffffffu, v, o);
    if (lane == 0) red[w] = v;
    __syncthreads();
    float r = 0.f;
    if (w == 0) {
        r = (lane < NWARP) ? red[lane] : 0.f;
        #pragma unroll
        for (int o = 8; o; o >>= 1) r += __shfl_down_sync(0xffffffffu, r, o);
    }
    __syncthreads();
    return r;
}

__device__ __forceinline__ void applyOne(int src, int dst) {
    unsigned m = g_newMask[dst];
    while (m) {
        int c = __ffs(m) - 1; m &= m - 1;
        atomicAdd(&g_counts[(size_t)src * 2 + (c >> 2)], 1u << ((c & 3) * 8));
    }
}

#define PROBE4(dd, jj) do {                                                    \
    unsigned _h0 = (sh.bmp[(unsigned)(dd).x >> 5] >> ((dd).x & 31)) & 1u;      \
    unsigned _h1 = (sh.bmp[(unsigned)(dd).y >> 5] >> ((dd).y & 31)) & 1u;      \
    unsigned _h2 = (sh.bmp[(unsigned)(dd).z >> 5] >> ((dd).z & 31)) & 1u;      \
    unsigned _h3 = (sh.bmp[(unsigned)(dd).w >> 5] >> ((dd).w & 31)) & 1u;      \
    if (_h0 | _h1 | _h2 | _h3) {                                               \
        int4 _s = s4[jj];                                                      \
        if (_h0) applyOne(_s.x, (dd).x);                                       \
        if (_h1) applyOne(_s.y, (dd).y);                                       \
        if (_h2) applyOne(_s.z, (dd).z);                                       \
        if (_h3) applyOne(_s.w, (dd).w);                                       \
    } } while (0)

// streaming edge scan over scan blocks [GEMMB, NB); 2-deep pipelined
__device__ void edgeScan(SH& sh, const int* __restrict__ esrc,
                         const int* __restrict__ edst, int E, int bid, int NB) {
    for (int i = threadIdx.x; i < BMPW; i += NT) sh.bmp[i] = g_bitmap[i];
    __syncthreads();
    int sid = (bid - GEMMB) * NT + threadIdx.x;
    int ST  = (NB - GEMMB) * NT;
    int e4 = E >> 2;
    const int4* d4 = (const int4*)edst;
    const int4* s4 = (const int4*)esrc;
    int j = sid;
    for (; j + ST < e4; j += 2 * ST) {
        int4 da = d4[j];
        int4 db = d4[j + ST];
        PROBE4(da, j);
        PROBE4(db, j + ST);
    }
    for (; j < e4; j += ST) {
        int4 da = d4[j];
        PROBE4(da, j);
    }
    if (sid == 0) {
        for (int e = e4 << 2; e < E; ++e) {
            int d = edst[e];
            if ((g_bitmap[(unsigned)d >> 5] >> (d & 31)) & 1u) applyOne(esrc[e], d);
        }
    }
}

// warp computes norm + 8 class dots for a 256-float row vs smem hx
// lane 0 gets results in dots[0..7], *den
__device__ __forceinline__ void warpScore(const float* __restrict__ esrow,
                                          const float* hxs, float* dots, float* den) {
    int lane = threadIdx.x & 31;
    const float4* r4 = (const float4*)(esrow + lane * 8);
    float4 a = r4[0], b = r4[1];
    float x[8] = {a.x, a.y, a.z, a.w, b.x, b.y, b.z, b.w};
    float acc[9];
    #pragma unroll
    for (int k = 0; k < 9; k++) acc[k] = 0.f;
    #pragma unroll
    for (int k = 0; k < 8; k++) acc[8] += x[k] * x[k];
    #pragma unroll
    for (int c = 0; c < NC; c++) {
        const float* h = hxs + c * F + lane * 8;
        #pragma unroll
        for (int k = 0; k < 8; k++) acc[c] += x[k] * h[k];
    }
    #pragma unroll
    for (int o = 16; o; o >>= 1) {
        #pragma unroll
        for (int k = 0; k < 9; k++)
            acc[k] += __shfl_down_sync(0xffffffffu, acc[k], o);
    }
    #pragma unroll
    for (int c = 0; c < NC; c++) dots[c] = acc[c];
    *den = sqrtf(acc[8]) + EPSF;
}

__global__ __launch_bounds__(NT, 1) void fused_kernel(
    const int* __restrict__ seeds, const int* __restrict__ esrc,
    const int* __restrict__ edst, const float* __restrict__ es,
    const float* __restrict__ W_ih, const float* __restrict__ W_hh,
    const float* __restrict__ b_ih, const float* __restrict__ b_hh,
    float* __restrict__ out, int E, int n)
{
    __shared__ SH sh;
    __shared__ float redsm[NWARP];
    __shared__ unsigned sBase;
    const int NB = gridDim.x;
    const int tid = threadIdx.x, bid = blockIdx.x;
    const int gid = bid * NT + tid, GT = NB * NT;
    const int wid = tid >> 5, lane = tid & 31;

    if (tid == 0) sBase = *(volatile unsigned*)&g_barGen;
    __syncthreads();
    const unsigned barBase = sBase;
    unsigned nbar = 0;

    // ---- P0: zero state ----
    for (int i = gid; i < 2 * n; i += GT) g_counts[i] = 0u;
    for (int i = gid; i < n; i += GT) {
        g_entity[i] = 0; g_cg[i] = 0u; g_newMask[i] = 0u;
    }
    for (int i = gid; i < BMPW; i += GT) g_bitmap[i] = 0u;
    for (int i = gid; i < NC * F; i += GT) g_hx[i] = 0.f;
    if (gid == 0) g_candCount = 0;
    gsync(barBase, nbar, NB);

    // ---- P1: seed marks + pool from seeds ----
    if (bid == 0 && tid < NC * SC) {
        int s = seeds[tid], c = tid >> 4;
        g_entity[s] = 1;
        atomicOr(&g_cg[s], 1u << c);
        atomicOr(&g_newMask[s], 1u << c);
        atomicOr(&g_bitmap[(unsigned)s >> 5], 1u << (s & 31));
        g_markNode[tid] = s;
    }
    if (bid >= 1 && bid <= NC && tid < F) {
        int c = bid - 1;
        float s = 0.f;
        #pragma unroll
        for (int j = 0; j < SC; j++)
            s += es[(size_t)seeds[c * SC + j] * F + tid];
        g_inp[c * F + tid] = s * (1.0f / SC);
    }
    gsync(barBase, nbar, NB);

    for (int step = 0; step < NSTEP; step++) {
        int mm = (step == 0) ? 3 : 2;

        // ---- A: gemm (blocks < GEMMB)  ||  edge scan (blocks >= GEMMB) ----
        if (gid == 0) g_candCount = 0;
        if (bid < GEMMB) {
            for (int i = tid; i < NC * F; i += NT) {
                sh.shv[i] = g_inp[i];
                sh.shv[NC * F + i] = g_hx[i];
            }
            __syncthreads();
            int warp = bid * NWARP + wid;
            int totalW = GEMMB * NWARP;
            for (int job = warp; job < 2 * 3 * F; job += totalW) {
                int m = (job >= 3 * F) ? 1 : 0;
                int r = job - m * 3 * F;
                const float4* w4 = (const float4*)((m ? W_hh : W_ih) + (size_t)r * F);
                float4 a = w4[lane * 2], b = w4[lane * 2 + 1];
                float wv[8] = {a.x, a.y, a.z, a.w, b.x, b.y, b.z, b.w};
                const float* vecb = sh.shv + m * NC * F;
                #pragma unroll
                for (int c = 0; c < NC; c++) {
                    const float* v = vecb + c * F + lane * 8;
                    float d = wv[0]*v[0] + wv[1]*v[1] + wv[2]*v[2] + wv[3]*v[3]
                            + wv[4]*v[4] + wv[5]*v[5] + wv[6]*v[6] + wv[7]*v[7];
                    #pragma unroll
                    for (int o = 16; o; o >>= 1) d += __shfl_down_sync(0xffffffffu, d, o);
                    if (lane == 0) (m ? g_gh : g_gi)[c * 3 * F + r] = d;
                }
            }
        } else {
            edgeScan(sh, esrc, edst, E, bid, NB);
        }
        gsync(barBase, nbar, NB);

        // ---- B: gate (blocks 0-7)  ||  valid scan + clears (blocks 8+) ----
        if (bid < NC) {
            int c = bid;
            float h = 0.f;
            if (tid < F) {
                int k = tid;
                float gir = g_gi[c*3*F + k]       + b_ih[k];
                float giz = g_gi[c*3*F + F + k]   + b_ih[F + k];
                float gin = g_gi[c*3*F + 2*F + k] + b_ih[2*F + k];
                float ghr = g_gh[c*3*F + k]       + b_hh[k];
                float ghz = g_gh[c*3*F + F + k]   + b_hh[F + k];
                float ghn = g_gh[c*3*F + 2*F + k] + b_hh[2*F + k];
                float r = 1.f / (1.f + expf(-(gir + ghr)));
                float z = 1.f / (1.f + expf(-(giz + ghz)));
                float nn = tanhf(gin + r * ghn);
                h = (1.f - z) * nn + z * g_hx[c * F + k];
                g_hx[c * F + k] = h;
                out[HX_OFF + step * NC * F + c * F + k] = h;
            }
            float s2 = blockSumAll(h * h, redsm);
            if (tid == 0) g_hxden[c] = sqrtf(s2) + EPSF;
        } else {
            if (bid == NC && tid < NC * SC) g_newMask[g_markNode[tid]] = 0u;
            int start = (bid - NC) * NT + tid, stride = (NB - NC) * NT;
            for (int i = start; i < BMPW; i += stride) g_bitmap[i] = 0u;
            for (int i = start; i < n; i += stride) {
                unsigned vm = 0;
                if (!g_entity[i]) {
                    uint2 u = *(const uint2*)&g_counts[(size_t)i * 2];
                    #pragma unroll
                    for (int c = 0; c < 4; c++)
                        if (((u.x >> (c * 8)) & 0xffu) >= (unsigned)mm) vm |= 1u << c;
                    #pragma unroll
                    for (int c = 0; c < 4; c++)
                        if (((u.y >> (c * 8)) & 0xffu) >= (unsigned)mm) vm |= 1u << (c + 4);
                }
                g_valid[i] = (unsigned char)vm;
                if (vm) {
                    int p = atomicAdd(&g_candCount, 1);
                    if (p < CANDCAP) g_cand[p] = i;
                }
            }
        }
        gsync(barBase, nbar, NB);

        // ---- C: score candidates (warp per candidate) ----
        {
            int cc = g_candCount; if (cc > CANDCAP) cc = CANDCAP;
            for (int i = tid; i < NC * F; i += NT) sh.hxsc[i] = g_hx[i];
            __syncthreads();
            int warpG = bid * NWARP + wid;
            for (int ci = warpG; ci < cc; ci += NB * NWARP) {
                int node = g_cand[ci];
                float dots[NC], den;
                warpScore(es + (size_t)node * F, sh.hxsc, dots, &den);
                if (lane == 0) {
                    #pragma unroll
                    for (int c = 0; c < NC; c++)
                        g_candScore[ci * NC + c] =
                            0.5f * (dots[c] / (den * g_hxden[c])) + 0.5f;
                }
            }
        }
        gsync(barBase, nbar, NB);

        // ---- D: select + finalize + pool (blocks 0-7, one per class) ----
        if (bid < NC) {
            int c = bid;
            int cc = g_candCount; if (cc > CANDCAP) cc = CANDCAP;
            for (int i = tid; i < NC * F; i += NT) sh.sel.hxs[i] = g_hx[i];
            for (int i = tid; i < CANDCAP / 32; i += NT) sh.sel.ch[i] = 0u;
            __syncthreads();
            int slot = 0;
            for (; slot < SC; ++slot) {
                unsigned long long best = 0ull;
                for (int j = tid; j < cc; j += NT) {
                    int nd = g_cand[j];
                    if (((g_valid[nd] >> c) & 1u) && !((sh.sel.ch[j >> 5] >> (j & 31)) & 1u)) {
                        unsigned u = __float_as_uint(g_candScore[j * NC + c]);
                        u ^= (u & 0x80000000u) ? 0xffffffffu : 0x80000000u;
                        unsigned long long k = (((unsigned long long)u) << 32)
                                             | (unsigned long long)(0xffffffffu - (unsigned)nd);
                        if (k > best) best = k;
                    }
                }
                #pragma unroll
                for (int o = 16; o; o >>= 1) {
                    unsigned long long v = __shfl_down_sync(0xffffffffu, best, o);
                    if (v > best) best = v;
                }
                if (lane == 0) sh.sel.red[wid] = best;
                __syncthreads();
                if (wid == 0) {
                    unsigned long long v = (lane < NWARP) ? sh.sel.red[lane] : 0ull;
                    #pragma unroll
                    for (int o = 8; o; o >>= 1) {
                        unsigned long long w = __shfl_down_sync(0xffffffffu, v, o);
                        if (w > v) v = w;
                    }
                    if (lane == 0) sh.sel.bestk = v;
                }
                __syncthreads();
                unsigned long long bk = sh.sel.bestk;
                if (bk == 0ull) break;
                int node = (int)(0xffffffffu - (unsigned)(bk & 0xffffffffu));
                for (int j = tid; j < cc; j += NT)
                    if (g_cand[j] == node) sh.sel.ch[j >> 5] |= (1u << (j & 31));
                if (tid == 0) {
                    sh.sel.snode[slot] = node;
                    out[SEL_OFF + step * NC * SC + c * SC + slot] = (float)node;
                }
                __syncthreads();
            }
            if (tid == 0) {
                int p = 0;
                for (; slot < SC; ++slot) {
                    while ((g_valid[p] >> c) & 1u) ++p;
                    sh.sel.snode[slot] = p;
                    out[SEL_OFF + step * NC * SC + c * SC + slot] = (float)p;
                    ++p;
                }
                out[STEP_OFF + step * NC + c] = 16.0f;
            }
            __syncthreads();
            // marks
            if (tid < SC) {
                int node = sh.sel.snode[tid];
                unsigned old = atomicOr(&g_cg[node], 1u << c);
                g_entity[node] = 1;
                g_markNode[c * SC + tid] = node;
                if (!((old >> c) & 1u)) {
                    atomicOr(&g_newMask[node], 1u << c);
                    atomicOr(&g_bitmap[(unsigned)node >> 5], 1u << (node & 31));
                }
            }
            // output rows: warp j -> slot j
            {
                int node = sh.sel.snode[wid];
                unsigned vm = g_valid[node];
                float* orow = out + OUT_OFF + step * (NC * SC * NC) + (c * SC + wid) * NC;
                if (vm == 0u) {
                    if (lane < NC) orow[lane] = 0.f;
                } else {
                    float dots[NC], den;
                    warpScore(es + (size_t)node * F, sh.sel.hxs, dots, &den);
                    if (lane == 0) {
                        #pragma unroll
                        for (int c2 = 0; c2 < NC; c2++)
                            orow[c2] = 0.5f * (dots[c2] / (den * g_hxden[c2])) + 0.5f;
                    }
                }
            }
            __syncthreads();
            // pool for next step
            if (step < NSTEP - 1 && tid < F) {
                float s = 0.f;
                #pragma unroll
                for (int j = 0; j < SC; j++)
                    s += es[(size_t)sh.sel.snode[j] * F + tid];
                g_inp[c * F + tid] = s * (1.0f / SC);
            }
        }
        gsync(barBase, nbar, NB);
    }
}

// ---------------- launch ----------------
extern "C" void kernel_launch(void* const* d_in, const int* in_sizes, int n_in,
                              void* d_out, int out_size) {
    const int*   seeds = (const int*)d_in[0];
    const int*   esrc  = (const int*)d_in[1];
    const int*   edst  = (const int*)d_in[2];
    const float* es    = (const float*)d_in[3];
    const float* W_ih  = (const float*)d_in[4];
    const float* W_hh  = (const float*)d_in[5];
    const float* b_ih  = (const float*)d_in[6];
    const float* b_hh  = (const float*)d_in[7];
    float* out = (float*)d_out;
    int E = in_sizes[1];
    int n = in_sizes[3] / F;

    int dev = 0, nsm = 0;
    cudaGetDevice(&dev);
    cudaDeviceGetAttribute(&nsm, cudaDevAttrMultiProcessorCount, dev);
    if (nsm <= 0 || nsm > 512) nsm = 148;

    fused_kernel<<<nsm, NT>>>(seeds, esrc, edst, es, W_ih, W_hh, b_ih, b_hh, out, E, n);
}